// round 13
// baseline (speedup 1.0000x reference)
#include <cuda_runtime.h>

// ---------------- scratch (device globals; zero-initialized) ---------------
__device__ float g_pooledp[16*256*32];     // [b][cs][32] padded, pads stay 0
__device__ float g_dots[1281];             // Wq^T bk | Wk^T bq | bq.bk
__device__ float g_wqk[1024*256];          // Wq^T Wk  [cr][cs]
__device__ float g_kq[16*1024*32];         // [b][cr][32]
__device__ float g_v[16*1024*32];          // [b][cr][32]
__device__ float g_bqk[16*32];             // [b][32]
__device__ float g_epart[4*16*784*32];     // [z][b][n][32]
__device__ float g_attn_t[16*25*784];      // [b][s][n]  TRANSPOSED attention
__device__ int   g_cnt[16*7];              // completion counters [b][ntile]

// ---------------- packed f32x2 helpers -------------------------------------
__device__ __forceinline__ unsigned long long pack2(float lo, float hi) {
    unsigned long long r;
    asm("mov.b64 %0, {%1,%2};" : "=l"(r) : "f"(lo), "f"(hi));
    return r;
}
__device__ __forceinline__ float2 unpack2(unsigned long long v) {
    float2 r;
    asm("mov.b64 {%0,%1}, %2;" : "=f"(r.x), "=f"(r.y) : "l"(v));
    return r;
}
__device__ __forceinline__ void fma2(unsigned long long& d,
                                     unsigned long long a,
                                     unsigned long long b) {
    asm("fma.rn.f32x2 %0, %1, %2, %0;" : "+l"(d) : "l"(a), "l"(b));
}
__device__ __forceinline__ void add2(unsigned long long& d,
                                     unsigned long long a) {
    asm("add.rn.f32x2 %0, %0, %1;" : "+l"(d) : "l"(a));
}

// ---------------------------------------------------------------------------
// k_prep: gemm0 (0..255) | dots1 (256..287) | dots2 (288..295) | dots3 (296)
//         | pool (297..1896)
// ---------------------------------------------------------------------------
__global__ __launch_bounds__(128) void k_prep(const float* __restrict__ Wq,
                                              const float* __restrict__ bq,
                                              const float* __restrict__ Wk,
                                              const float* __restrict__ bk,
                                              const float* __restrict__ xs_in) {
    __shared__ float sm[1664];
    int bid = blockIdx.x;
    int t = threadIdx.x;

    if (bid < 256) {
        float* As = sm;          // [16][32]
        float* Bs = sm + 512;    // [16][32]
        int m0 = (bid >> 3) * 32, n0 = (bid & 7) * 32;
        int tx = t & 7, ty = t >> 3;
        unsigned long long acc2[2][2] = {};
        for (int k0 = 0; k0 < 512; k0 += 16) {
            #pragma unroll
            for (int u = 0; u < 4; u++) {
                int idx = t + u * 128;
                int kk = idx >> 5, mm = idx & 31;
                As[idx] = Wq[(k0+kk)*1024 + m0 + mm];
                Bs[idx] = Wk[(k0+kk)*256 + n0 + mm];
            }
            __syncthreads();
            #pragma unroll
            for (int kk = 0; kk < 16; kk++) {
                float2 a2 = *(const float2*)&As[kk*32 + ty*2];
                ulonglong2 b2 = *(const ulonglong2*)&Bs[kk*32 + tx*4];
                unsigned long long pa0 = pack2(a2.x, a2.x);
                unsigned long long pa1 = pack2(a2.y, a2.y);
                fma2(acc2[0][0], pa0, b2.x);
                fma2(acc2[0][1], pa0, b2.y);
                fma2(acc2[1][0], pa1, b2.x);
                fma2(acc2[1][1], pa1, b2.y);
            }
            __syncthreads();
        }
        #pragma unroll
        for (int i = 0; i < 2; i++) {
            float2 p0 = unpack2(acc2[i][0]), p1 = unpack2(acc2[i][1]);
            *(float4*)&g_wqk[(m0 + ty*2 + i)*256 + n0 + tx*4] =
                make_float4(p0.x, p0.y, p1.x, p1.y);
        }
    } else if (bid < 288) {
        int lane = t & 31, slice = t >> 5;
        int c = (bid - 256) * 32 + lane;
        float acc = 0.f;
        int kbase = slice * 128;
        #pragma unroll 8
        for (int i = 0; i < 128; i++)
            acc += Wq[(kbase + i)*1024 + c] * bk[kbase + i];
        sm[t] = acc; __syncthreads();
        if (t < 32)
            g_dots[(bid - 256)*32 + t] = sm[t] + sm[t+32] + sm[t+64] + sm[t+96];
    } else if (bid < 296) {
        int lane = t & 31, slice = t >> 5;
        int c = (bid - 288) * 32 + lane;
        float acc = 0.f;
        int kbase = slice * 128;
        #pragma unroll 8
        for (int i = 0; i < 128; i++)
            acc += Wk[(kbase + i)*256 + c] * bq[kbase + i];
        sm[t] = acc; __syncthreads();
        if (t < 32)
            g_dots[1024 + (bid - 288)*32 + t] = sm[t] + sm[t+32] + sm[t+64] + sm[t+96];
    } else if (bid == 296) {
        float acc = 0.f;
        for (int i = t; i < 512; i += 128) acc += bq[i] * bk[i];
        sm[t] = acc; __syncthreads();
        for (int st = 64; st > 0; st >>= 1) {
            if (t < st) sm[t] += sm[t + st];
            __syncthreads();
        }
        if (t == 0) g_dots[1280] = sm[0];
    } else {
        int r0 = (bid - 297) * 64;
        const float* src = xs_in + (size_t)r0 * 25;
        for (int i = t; i < 1600; i += 128) sm[i] = src[i];
        __syncthreads();
        if (t < 64) {
            float s = 0.f;
            #pragma unroll
            for (int w = 0; w < 25; w++) s += sm[t*25 + w];
            int o = r0 + t;
            int bc = o / 25, s_idx = o - bc * 25;
            g_pooledp[bc*32 + s_idx] = s * (1.0f / 25.0f);
        }
    }
}

// ---------------------------------------------------------------------------
// k_gemm1: [kq; v; bqk](b) = [Wqk; Wv; wkbq] @ pooledp_b + bias
// grid(17, 16), 256 thr (8 warps). BM=128, S=32, BK=32. thread 4m x 4s.
// ---------------------------------------------------------------------------
__global__ __launch_bounds__(256) void k_gemm1(const float* __restrict__ Wv,
                                               const float* __restrict__ bv) {
    __shared__ float As[32*132];
    __shared__ float Bs[32*32];
    int bx = blockIdx.x;
    int b  = blockIdx.y;
    int m0 = bx * 128;
    int t = threadIdx.x;
    int row = t >> 1, half = t & 1;
    int tx = t & 7, ty = t >> 3;
    unsigned long long acc2[4][2] = {};

    const float* arow;
    bool arow_valid;
    if (bx < 8)       { arow = g_wqk + (size_t)(m0 + row) * 256; arow_valid = true; }
    else if (bx < 16) { arow = Wv + (size_t)(m0 - 1024 + row) * 256; arow_valid = true; }
    else              { arow = g_dots + 1024; arow_valid = (row == 0); }

    for (int k0 = 0; k0 < 256; k0 += 32) {
        if (arow_valid) {
            #pragma unroll
            for (int u = 0; u < 4; u++) {
                int koff = half*16 + u*4;
                float4 a4 = *(const float4*)&arow[k0 + koff];
                As[(koff+0)*132 + row] = a4.x;
                As[(koff+1)*132 + row] = a4.y;
                As[(koff+2)*132 + row] = a4.z;
                As[(koff+3)*132 + row] = a4.w;
            }
        } else {
            #pragma unroll
            for (int u = 0; u < 4; u++) {
                int koff = half*16 + u*4;
                As[(koff+0)*132 + row] = 0.f;
                As[(koff+1)*132 + row] = 0.f;
                As[(koff+2)*132 + row] = 0.f;
                As[(koff+3)*132 + row] = 0.f;
            }
        }
        const float4* bsrc = (const float4*)(g_pooledp + ((b << 8) + k0) * 32);
        ((float4*)Bs)[t] = bsrc[t];
        __syncthreads();
        #pragma unroll 8
        for (int kk = 0; kk < 32; kk++) {
            float4 a4 = *(const float4*)&As[kk*132 + ty*4];
            ulonglong2 b2 = *(const ulonglong2*)&Bs[kk*32 + tx*4];
            unsigned long long pa[4] = {pack2(a4.x,a4.x), pack2(a4.y,a4.y),
                                        pack2(a4.z,a4.z), pack2(a4.w,a4.w)};
            #pragma unroll
            for (int i = 0; i < 4; i++) {
                fma2(acc2[i][0], pa[i], b2.x);
                fma2(acc2[i][1], pa[i], b2.y);
            }
        }
        __syncthreads();
    }
    int s0 = tx * 4;
    #pragma unroll
    for (int i = 0; i < 4; i++) {
        int m = m0 + ty*4 + i;
        float2 p0 = unpack2(acc2[i][0]), p1 = unpack2(acc2[i][1]);
        if (bx < 8) {
            float d = g_dots[m];
            *(float4*)&g_kq[((b << 10) + m)*32 + s0] =
                make_float4(p0.x+d, p0.y+d, p1.x+d, p1.y+d);
        } else if (bx < 16) {
            float d = bv[m - 1024];
            *(float4*)&g_v[((b << 10) + (m - 1024))*32 + s0] =
                make_float4(p0.x+d, p0.y+d, p1.x+d, p1.y+d);
        } else if (m == 2048) {
            float d = g_dots[1280];
            *(float4*)&g_bqk[b*32 + s0] =
                make_float4(p0.x+d, p0.y+d, p1.x+d, p1.y+d);
        }
    }
}

// ---------------------------------------------------------------------------
// k_energy: epart[z,b,n,s] = sum_{c in z-chunk} x[c,n]*kq[c,s], then the
// LAST z-block for each (n-tile,b) sums partials, softmaxes, writes attn_t.
// grid(7, 16, 4), 224 thr. Compute: 112 slots (8n x 4s, n-pair form) x 2
// c-halves, packed-f32x2 smem reduction at the end.
// ---------------------------------------------------------------------------
__global__ __launch_bounds__(224) void k_energy(const float* __restrict__ x) {
    __shared__ __align__(16) float xs[64*112];
    __shared__ float kqs[64*32];
    __shared__ int s_last;
    int n0 = blockIdx.x * 112;
    int b  = blockIdx.y;
    int z  = blockIdx.z;
    int t = threadIdx.x;
    int lq = t % 28, lc = t / 28;           // load mapping (unchanged)
    int h  = (t >= 112) ? 1 : 0;            // c-half
    int u  = t - h*112;
    int nq8 = u % 14, sg = u / 14;          // 14 n-octets x 8 s-quads
    unsigned long long acc2[4][4] = {};     // [n-pair][s]

    for (int cz = 0; cz < 4; cz++) {
        int cbase = z * 256 + cz * 64;
        const float4* xsrc = (const float4*)x
            + (size_t)((b << 10) + cbase) * 196 + (n0 >> 2);
        #pragma unroll
        for (int uu = 0; uu < 8; uu++) {
            int cc = lc + uu * 8;
            *(float4*)&xs[cc*112 + lq*4] = xsrc[(size_t)cc*196 + lq];
        }
        const float4* kq4 = (const float4*)(g_kq + (size_t)((b << 10) + cbase)*32);
        float4* kqs4 = (float4*)kqs;
        kqs4[t] = kq4[t];
        if (t + 224 < 512) kqs4[t + 224] = kq4[t + 224];
        if (t < 512 - 448) kqs4[t + 448] = kq4[t + 448];
        __syncthreads();
        int cb2 = h * 32;
        #pragma unroll 8
        for (int cc2 = 0; cc2 < 32; cc2++) {
            int cc = cb2 + cc2;
            ulonglong2 xa = *(const ulonglong2*)&xs[cc*112 + nq8*8];
            ulonglong2 xb = *(const ulonglong2*)&xs[cc*112 + nq8*8 + 4];
            float4 kv = *(const float4*)&kqs[cc*32 + sg*4];
            unsigned long long pk[4] = {pack2(kv.x,kv.x), pack2(kv.y,kv.y),
                                        pack2(kv.z,kv.z), pack2(kv.w,kv.w)};
            unsigned long long xp[4] = {xa.x, xa.y, xb.x, xb.y};
            #pragma unroll
            for (int p = 0; p < 4; p++) {
                fma2(acc2[p][0], xp[p], pk[0]);
                fma2(acc2[p][1], xp[p], pk[1]);
                fma2(acc2[p][2], xp[p], pk[2]);
                fma2(acc2[p][3], xp[p], pk[3]);
            }
        }
        __syncthreads();
    }

    // ---- c-half reduction (reuse xs as u64 staging: 112*16*8 = 14336 B) ----
    unsigned long long* red = (unsigned long long*)xs;
    if (h == 1) {
        #pragma unroll
        for (int p = 0; p < 4; p++)
            #pragma unroll
            for (int si = 0; si < 4; si++)
                red[(u*16) + p*4 + si] = acc2[p][si];
    }
    __syncthreads();
    if (h == 0) {
        #pragma unroll
        for (int p = 0; p < 4; p++)
            #pragma unroll
            for (int si = 0; si < 4; si++)
                add2(acc2[p][si], red[(u*16) + p*4 + si]);

        float* ep = g_epart + (size_t)(z*16 + b)*784*32;
        #pragma unroll
        for (int p = 0; p < 4; p++) {
            float2 q0 = unpack2(acc2[p][0]), q1 = unpack2(acc2[p][1]);
            float2 q2 = unpack2(acc2[p][2]), q3 = unpack2(acc2[p][3]);
            int n_even = n0 + nq8*8 + p*2;
            *(float4*)&ep[(size_t)n_even*32 + sg*4] =
                make_float4(q0.x, q1.x, q2.x, q3.x);
            *(float4*)&ep[(size_t)(n_even+1)*32 + sg*4] =
                make_float4(q0.y, q1.y, q2.y, q3.y);
        }
    }

    // ---- last-block-arrives softmax ----
    __threadfence();
    __syncthreads();
    if (t == 0)
        s_last = (atomicAdd(&g_cnt[b*7 + blockIdx.x], 1) == 3) ? 1 : 0;
    __syncthreads();
    if (s_last == 0) return;

    if (t < 112) {
        int n = n0 + t;
        const size_t part = (size_t)16*784*32;
        const float* base = g_epart + ((size_t)b*784 + n)*32;
        float4 v0 = *(const float4*)base;
        float4 v1 = *(const float4*)(base + 4);
        float4 v2 = *(const float4*)(base + 8);
        float4 v3 = *(const float4*)(base + 12);
        float4 v4 = *(const float4*)(base + 16);
        float4 v5 = *(const float4*)(base + 20);
        float4 v6 = *(const float4*)(base + 24);
        #pragma unroll
        for (int zz = 1; zz < 4; zz++) {
            const float* bz = base + zz*part;
            float4 u0 = *(const float4*)bz;
            float4 u1 = *(const float4*)(bz + 4);
            float4 u2 = *(const float4*)(bz + 8);
            float4 u3 = *(const float4*)(bz + 12);
            float4 u4 = *(const float4*)(bz + 16);
            float4 u5 = *(const float4*)(bz + 20);
            float4 u6 = *(const float4*)(bz + 24);
            v0.x+=u0.x; v0.y+=u0.y; v0.z+=u0.z; v0.w+=u0.w;
            v1.x+=u1.x; v1.y+=u1.y; v1.z+=u1.z; v1.w+=u1.w;
            v2.x+=u2.x; v2.y+=u2.y; v2.z+=u2.z; v2.w+=u2.w;
            v3.x+=u3.x; v3.y+=u3.y; v3.z+=u3.z; v3.w+=u3.w;
            v4.x+=u4.x; v4.y+=u4.y; v4.z+=u4.z; v4.w+=u4.w;
            v5.x+=u5.x; v5.y+=u5.y; v5.z+=u5.z; v5.w+=u5.w;
            v6.x+=u6.x; v6.y+=u6.y; v6.z+=u6.z; v6.w+=u6.w;
        }
        float e[25] = {v0.x,v0.y,v0.z,v0.w, v1.x,v1.y,v1.z,v1.w,
                       v2.x,v2.y,v2.z,v2.w, v3.x,v3.y,v3.z,v3.w,
                       v4.x,v4.y,v4.z,v4.w, v5.x,v5.y,v5.z,v5.w, v6.x};
        float mx = -1e30f;
        #pragma unroll
        for (int s = 0; s < 25; s++) {
            e[s] += g_bqk[b*32 + s];
            mx = fmaxf(mx, e[s]);
        }
        float sum = 0.f;
        #pragma unroll
        for (int s = 0; s < 25; s++) { e[s] = __expf(e[s] - mx); sum += e[s]; }
        float inv = 1.f / sum;
        float* at = g_attn_t + (size_t)b*25*784 + n;
        #pragma unroll
        for (int s = 0; s < 25; s++) at[(size_t)s*784] = e[s] * inv;
    }
    if (t == 0) g_cnt[b*7 + blockIdx.x] = 0;
}

// ---------------------------------------------------------------------------
// k_out: out[c,n] = x[c,n] + gamma * sum_s v[c,s]*attn_t[s,n]
// grid(7 n-tiles of 112, 8 c-tiles of 128, 16 b), 224 thr. thread 8c x 8n.
// ---------------------------------------------------------------------------
__global__ __launch_bounds__(224, 2) void k_out(const float* __restrict__ x,
                                                const float* __restrict__ gamma_p,
                                                float* __restrict__ out) {
    __shared__ float attn_ts[25*112];   // [s][n] straight coalesced copy
    __shared__ float v_ts[25*132];      // [s][c] transpose load
    int n0 = blockIdx.x * 112;
    int c0 = blockIdx.y * 128;
    int b  = blockIdx.z;
    int t = threadIdx.x;

    const float4* at4 = (const float4*)(g_attn_t + (size_t)b*25*784) + (n0 >> 2);
    #pragma unroll
    for (int u = 0; u < 4; u++) {
        int i = t + u*224;
        if (i < 700) {
            int s = i / 28, q = i - s*28;
            ((float4*)attn_ts)[s*28 + q] = at4[(size_t)s*196 + q];
        }
    }
    const float4* v4p = (const float4*)(g_v + (size_t)((b << 10) + c0)*32);
    #pragma unroll
    for (int u = 0; u < 5; u++) {
        int i = t + u*224;
        if (i < 1024) {
            int row = i >> 3, q = i & 7;
            float4 a4 = v4p[row*8 + q];
            int s = q*4;
            if (s   < 25) v_ts[(s  )*132 + row] = a4.x;
            if (s+1 < 25) v_ts[(s+1)*132 + row] = a4.y;
            if (s+2 < 25) v_ts[(s+2)*132 + row] = a4.z;
            if (s+3 < 25) v_ts[(s+3)*132 + row] = a4.w;
        }
    }
    __syncthreads();

    int ng = t % 14, cq = t / 14;       // 14 n-octets x 16 c-octets
    unsigned long long acc2[8][4] = {};
    #pragma unroll
    for (int s = 0; s < 25; s++) {
        float4 vlo = *(const float4*)&v_ts[s*132 + cq*8];
        float4 vhi = *(const float4*)&v_ts[s*132 + cq*8 + 4];
        const ulonglong2* ap = (const ulonglong2*)&attn_ts[s*112 + ng*8];
        ulonglong2 A0 = ap[0], A1 = ap[1];
        unsigned long long pv[8] = {
            pack2(vlo.x,vlo.x), pack2(vlo.y,vlo.y),
            pack2(vlo.z,vlo.z), pack2(vlo.w,vlo.w),
            pack2(vhi.x,vhi.x), pack2(vhi.y,vhi.y),
            pack2(vhi.z,vhi.z), pack2(vhi.w,vhi.w)};
        #pragma unroll
        for (int i = 0; i < 8; i++) {
            fma2(acc2[i][0], pv[i], A0.x);
            fma2(acc2[i][1], pv[i], A0.y);
            fma2(acc2[i][2], pv[i], A1.x);
            fma2(acc2[i][3], pv[i], A1.y);
        }
    }
    float gamma = gamma_p[0];
    #pragma unroll
    for (int i = 0; i < 8; i++) {
        int c = c0 + cq*8 + i;
        size_t off = (size_t)((b << 10) + c)*784 + n0 + ng*8;
        const float* xr = x + off;
        float* orow = out + off;
        float2 q0 = unpack2(acc2[i][0]), q1 = unpack2(acc2[i][1]);
        float2 q2 = unpack2(acc2[i][2]), q3 = unpack2(acc2[i][3]);
        float4 xa = *(const float4*)xr;
        float4 xc = *(const float4*)(xr + 4);
        *(float4*)orow = make_float4(fmaf(gamma,q0.x,xa.x), fmaf(gamma,q0.y,xa.y),
                                     fmaf(gamma,q1.x,xa.z), fmaf(gamma,q1.y,xa.w));
        *(float4*)(orow+4) = make_float4(fmaf(gamma,q2.x,xc.x), fmaf(gamma,q2.y,xc.y),
                                         fmaf(gamma,q3.x,xc.z), fmaf(gamma,q3.y,xc.w));
    }
}

// ---------------------------------------------------------------------------
extern "C" void kernel_launch(void* const* d_in, const int* in_sizes, int n_in,
                              void* d_out, int out_size) {
    const float* x_rgb  = (const float*)d_in[0];
    const float* x_skel = (const float*)d_in[1];
    const float* Wq     = (const float*)d_in[2];
    const float* bq     = (const float*)d_in[3];
    const float* Wk     = (const float*)d_in[4];
    const float* bk     = (const float*)d_in[5];
    const float* Wv     = (const float*)d_in[6];
    const float* bv     = (const float*)d_in[7];
    const float* gamma  = (const float*)d_in[8];
    float* out = (float*)d_out;

    k_prep  <<<1897, 128>>>(Wq, bq, Wk, bk, x_skel);
    k_gemm1 <<<dim3(17, 16), 256>>>(Wv, bv);
    k_energy<<<dim3(7, 16, 4), 224>>>(x_rgb);
    k_out   <<<dim3(7, 8, 16), 224>>>(x_rgb, gamma, out);
}

// round 14
// speedup vs baseline: 1.0936x; 1.0936x over previous
#include <cuda_runtime.h>

// ---------------- scratch (device globals; zero-initialized) ---------------
__device__ float g_pooledp[16*256*32];     // [b][cs][32] padded, pads stay 0
__device__ float g_dots[1281];             // Wq^T bk | Wk^T bq | bq.bk
__device__ float g_wqk[1024*256];          // Wq^T Wk  [cr][cs]
__device__ float g_kq[16*1024*32];         // [b][cr][32]
__device__ float g_v[16*1024*32];          // [b][cr][32]
__device__ float g_bqk[16*32];             // [b][32]
__device__ float g_epart[4*16*784*32];     // [z][b][n][32]
__device__ float g_attn_t[16*25*784];      // [b][s][n]  TRANSPOSED attention
__device__ int   g_cnt[16*7];              // completion counters [b][ntile]

// ---------------- packed f32x2 helpers -------------------------------------
__device__ __forceinline__ unsigned long long pack2(float lo, float hi) {
    unsigned long long r;
    asm("mov.b64 %0, {%1,%2};" : "=l"(r) : "f"(lo), "f"(hi));
    return r;
}
__device__ __forceinline__ float2 unpack2(unsigned long long v) {
    float2 r;
    asm("mov.b64 {%0,%1}, %2;" : "=f"(r.x), "=f"(r.y) : "l"(v));
    return r;
}
__device__ __forceinline__ void fma2(unsigned long long& d,
                                     unsigned long long a,
                                     unsigned long long b) {
    asm("fma.rn.f32x2 %0, %1, %2, %0;" : "+l"(d) : "l"(a), "l"(b));
}

// ---------------------------------------------------------------------------
// k_prep: gemm0 (0..255) | dots1 (256..287) | dots2 (288..295) | dots3 (296)
//         | pool (297..1896)
// ---------------------------------------------------------------------------
__global__ __launch_bounds__(128) void k_prep(const float* __restrict__ Wq,
                                              const float* __restrict__ bq,
                                              const float* __restrict__ Wk,
                                              const float* __restrict__ bk,
                                              const float* __restrict__ xs_in) {
    __shared__ float sm[1664];
    int bid = blockIdx.x;
    int t = threadIdx.x;

    if (bid < 256) {
        float* As = sm;          // [16][32]
        float* Bs = sm + 512;    // [16][32]
        int m0 = (bid >> 3) * 32, n0 = (bid & 7) * 32;
        int tx = t & 7, ty = t >> 3;
        unsigned long long acc2[2][2] = {};
        for (int k0 = 0; k0 < 512; k0 += 16) {
            #pragma unroll
            for (int u = 0; u < 4; u++) {
                int idx = t + u * 128;
                int kk = idx >> 5, mm = idx & 31;
                As[idx] = Wq[(k0+kk)*1024 + m0 + mm];
                Bs[idx] = Wk[(k0+kk)*256 + n0 + mm];
            }
            __syncthreads();
            #pragma unroll
            for (int kk = 0; kk < 16; kk++) {
                float2 a2 = *(const float2*)&As[kk*32 + ty*2];
                ulonglong2 b2 = *(const ulonglong2*)&Bs[kk*32 + tx*4];
                unsigned long long pa0 = pack2(a2.x, a2.x);
                unsigned long long pa1 = pack2(a2.y, a2.y);
                fma2(acc2[0][0], pa0, b2.x);
                fma2(acc2[0][1], pa0, b2.y);
                fma2(acc2[1][0], pa1, b2.x);
                fma2(acc2[1][1], pa1, b2.y);
            }
            __syncthreads();
        }
        #pragma unroll
        for (int i = 0; i < 2; i++) {
            float2 p0 = unpack2(acc2[i][0]), p1 = unpack2(acc2[i][1]);
            *(float4*)&g_wqk[(m0 + ty*2 + i)*256 + n0 + tx*4] =
                make_float4(p0.x, p0.y, p1.x, p1.y);
        }
    } else if (bid < 288) {
        int lane = t & 31, slice = t >> 5;
        int c = (bid - 256) * 32 + lane;
        float acc = 0.f;
        int kbase = slice * 128;
        #pragma unroll 8
        for (int i = 0; i < 128; i++)
            acc += Wq[(kbase + i)*1024 + c] * bk[kbase + i];
        sm[t] = acc; __syncthreads();
        if (t < 32)
            g_dots[(bid - 256)*32 + t] = sm[t] + sm[t+32] + sm[t+64] + sm[t+96];
    } else if (bid < 296) {
        int lane = t & 31, slice = t >> 5;
        int c = (bid - 288) * 32 + lane;
        float acc = 0.f;
        int kbase = slice * 128;
        #pragma unroll 8
        for (int i = 0; i < 128; i++)
            acc += Wk[(kbase + i)*256 + c] * bq[kbase + i];
        sm[t] = acc; __syncthreads();
        if (t < 32)
            g_dots[1024 + (bid - 288)*32 + t] = sm[t] + sm[t+32] + sm[t+64] + sm[t+96];
    } else if (bid == 296) {
        float acc = 0.f;
        for (int i = t; i < 512; i += 128) acc += bq[i] * bk[i];
        sm[t] = acc; __syncthreads();
        for (int st = 64; st > 0; st >>= 1) {
            if (t < st) sm[t] += sm[t + st];
            __syncthreads();
        }
        if (t == 0) g_dots[1280] = sm[0];
    } else {
        int r0 = (bid - 297) * 64;
        const float* src = xs_in + (size_t)r0 * 25;
        for (int i = t; i < 1600; i += 128) sm[i] = src[i];
        __syncthreads();
        if (t < 64) {
            float s = 0.f;
            #pragma unroll
            for (int w = 0; w < 25; w++) s += sm[t*25 + w];
            int o = r0 + t;
            int bc = o / 25, s_idx = o - bc * 25;
            g_pooledp[bc*32 + s_idx] = s * (1.0f / 25.0f);
        }
    }
}

// ---------------------------------------------------------------------------
// k_gemm1: [kq; v; bqk](b) = [Wqk; Wv; wkbq] @ pooledp_b + bias
// grid(17, 16), 256 thr (8 warps). BM=128, S=32, BK=32. thread 4m x 4s.
// ---------------------------------------------------------------------------
__global__ __launch_bounds__(256) void k_gemm1(const float* __restrict__ Wv,
                                               const float* __restrict__ bv) {
    __shared__ float As[32*132];
    __shared__ float Bs[32*32];
    int bx = blockIdx.x;
    int b  = blockIdx.y;
    int m0 = bx * 128;
    int t = threadIdx.x;
    int row = t >> 1, half = t & 1;
    int tx = t & 7, ty = t >> 3;
    unsigned long long acc2[4][2] = {};

    const float* arow;
    bool arow_valid;
    if (bx < 8)       { arow = g_wqk + (size_t)(m0 + row) * 256; arow_valid = true; }
    else if (bx < 16) { arow = Wv + (size_t)(m0 - 1024 + row) * 256; arow_valid = true; }
    else              { arow = g_dots + 1024; arow_valid = (row == 0); }

    for (int k0 = 0; k0 < 256; k0 += 32) {
        if (arow_valid) {
            #pragma unroll
            for (int u = 0; u < 4; u++) {
                int koff = half*16 + u*4;
                float4 a4 = *(const float4*)&arow[k0 + koff];
                As[(koff+0)*132 + row] = a4.x;
                As[(koff+1)*132 + row] = a4.y;
                As[(koff+2)*132 + row] = a4.z;
                As[(koff+3)*132 + row] = a4.w;
            }
        } else {
            #pragma unroll
            for (int u = 0; u < 4; u++) {
                int koff = half*16 + u*4;
                As[(koff+0)*132 + row] = 0.f;
                As[(koff+1)*132 + row] = 0.f;
                As[(koff+2)*132 + row] = 0.f;
                As[(koff+3)*132 + row] = 0.f;
            }
        }
        const float4* bsrc = (const float4*)(g_pooledp + ((b << 8) + k0) * 32);
        ((float4*)Bs)[t] = bsrc[t];
        __syncthreads();
        #pragma unroll 8
        for (int kk = 0; kk < 32; kk++) {
            float4 a4 = *(const float4*)&As[kk*132 + ty*4];
            ulonglong2 b2 = *(const ulonglong2*)&Bs[kk*32 + tx*4];
            unsigned long long pa[4] = {pack2(a4.x,a4.x), pack2(a4.y,a4.y),
                                        pack2(a4.z,a4.z), pack2(a4.w,a4.w)};
            #pragma unroll
            for (int i = 0; i < 4; i++) {
                fma2(acc2[i][0], pa[i], b2.x);
                fma2(acc2[i][1], pa[i], b2.y);
            }
        }
        __syncthreads();
    }
    int s0 = tx * 4;
    #pragma unroll
    for (int i = 0; i < 4; i++) {
        int m = m0 + ty*4 + i;
        float2 p0 = unpack2(acc2[i][0]), p1 = unpack2(acc2[i][1]);
        if (bx < 8) {
            float d = g_dots[m];
            *(float4*)&g_kq[((b << 10) + m)*32 + s0] =
                make_float4(p0.x+d, p0.y+d, p1.x+d, p1.y+d);
        } else if (bx < 16) {
            float d = bv[m - 1024];
            *(float4*)&g_v[((b << 10) + (m - 1024))*32 + s0] =
                make_float4(p0.x+d, p0.y+d, p1.x+d, p1.y+d);
        } else if (m == 2048) {
            float d = g_dots[1280];
            *(float4*)&g_bqk[b*32 + s0] =
                make_float4(p0.x+d, p0.y+d, p1.x+d, p1.y+d);
        }
    }
}

// ---------------------------------------------------------------------------
// k_energy: epart[z,b,n,s] = sum_{c in z-chunk} x[c,n]*kq[c,s], then the
// LAST z-block for each (n-tile,b) sums partials, softmaxes, writes attn_t.
// grid(7, 16, 4), 224 thr. thread 4n x 4s.  (R12-measured design)
// ---------------------------------------------------------------------------
__global__ __launch_bounds__(224) void k_energy(const float* __restrict__ x) {
    __shared__ float xs[64*112];
    __shared__ float kqs[64*32];
    __shared__ int s_last;
    int n0 = blockIdx.x * 112;
    int b  = blockIdx.y;
    int z  = blockIdx.z;
    int t = threadIdx.x;
    int nq = t % 28, sg = t / 28;
    unsigned long long acc2[4][2] = {};

    for (int cz = 0; cz < 4; cz++) {
        int cbase = z * 256 + cz * 64;
        const float4* xsrc = (const float4*)x
            + (size_t)((b << 10) + cbase) * 196 + (n0 >> 2);
        #pragma unroll
        for (int u = 0; u < 8; u++) {
            int cc = sg + u * 8;
            *(float4*)&xs[cc*112 + nq*4] = xsrc[(size_t)cc*196 + nq];
        }
        const float4* kq4 = (const float4*)(g_kq + (size_t)((b << 10) + cbase)*32);
        float4* kqs4 = (float4*)kqs;
        kqs4[t] = kq4[t];
        if (t + 224 < 512) kqs4[t + 224] = kq4[t + 224];
        if (t < 512 - 448) kqs4[t + 448] = kq4[t + 448];
        __syncthreads();
        #pragma unroll 8
        for (int cc = 0; cc < 64; cc++) {
            float4 x4 = *(const float4*)&xs[cc*112 + nq*4];
            ulonglong2 k2 = *(const ulonglong2*)&kqs[cc*32 + sg*4];
            unsigned long long px[4] = {pack2(x4.x,x4.x), pack2(x4.y,x4.y),
                                        pack2(x4.z,x4.z), pack2(x4.w,x4.w)};
            #pragma unroll
            for (int i = 0; i < 4; i++) {
                fma2(acc2[i][0], px[i], k2.x);
                fma2(acc2[i][1], px[i], k2.y);
            }
        }
        __syncthreads();
    }
    float* ep = g_epart + (size_t)(z*16 + b)*784*32;
    #pragma unroll
    for (int i = 0; i < 4; i++) {
        int n = n0 + nq*4 + i;
        float2 p0 = unpack2(acc2[i][0]), p1 = unpack2(acc2[i][1]);
        *(float4*)&ep[(size_t)n*32 + sg*4] = make_float4(p0.x, p0.y, p1.x, p1.y);
    }

    // ---- last-block-arrives softmax ----
    __threadfence();
    __syncthreads();
    if (t == 0)
        s_last = (atomicAdd(&g_cnt[b*7 + blockIdx.x], 1) == 3) ? 1 : 0;
    __syncthreads();
    if (s_last == 0) return;

    if (t < 112) {
        int n = n0 + t;
        const size_t part = (size_t)16*784*32;
        const float* base = g_epart + ((size_t)b*784 + n)*32;
        float4 v0 = *(const float4*)base;
        float4 v1 = *(const float4*)(base + 4);
        float4 v2 = *(const float4*)(base + 8);
        float4 v3 = *(const float4*)(base + 12);
        float4 v4 = *(const float4*)(base + 16);
        float4 v5 = *(const float4*)(base + 20);
        float4 v6 = *(const float4*)(base + 24);
        #pragma unroll
        for (int zz = 1; zz < 4; zz++) {
            const float* bz = base + zz*part;
            float4 u0 = *(const float4*)bz;
            float4 u1 = *(const float4*)(bz + 4);
            float4 u2 = *(const float4*)(bz + 8);
            float4 u3 = *(const float4*)(bz + 12);
            float4 u4 = *(const float4*)(bz + 16);
            float4 u5 = *(const float4*)(bz + 20);
            float4 u6 = *(const float4*)(bz + 24);
            v0.x+=u0.x; v0.y+=u0.y; v0.z+=u0.z; v0.w+=u0.w;
            v1.x+=u1.x; v1.y+=u1.y; v1.z+=u1.z; v1.w+=u1.w;
            v2.x+=u2.x; v2.y+=u2.y; v2.z+=u2.z; v2.w+=u2.w;
            v3.x+=u3.x; v3.y+=u3.y; v3.z+=u3.z; v3.w+=u3.w;
            v4.x+=u4.x; v4.y+=u4.y; v4.z+=u4.z; v4.w+=u4.w;
            v5.x+=u5.x; v5.y+=u5.y; v5.z+=u5.z; v5.w+=u5.w;
            v6.x+=u6.x; v6.y+=u6.y; v6.z+=u6.z; v6.w+=u6.w;
        }
        float e[25] = {v0.x,v0.y,v0.z,v0.w, v1.x,v1.y,v1.z,v1.w,
                       v2.x,v2.y,v2.z,v2.w, v3.x,v3.y,v3.z,v3.w,
                       v4.x,v4.y,v4.z,v4.w, v5.x,v5.y,v5.z,v5.w, v6.x};
        float mx = -1e30f;
        #pragma unroll
        for (int s = 0; s < 25; s++) {
            e[s] += g_bqk[b*32 + s];
            mx = fmaxf(mx, e[s]);
        }
        float sum = 0.f;
        #pragma unroll
        for (int s = 0; s < 25; s++) { e[s] = __expf(e[s] - mx); sum += e[s]; }
        float inv = 1.f / sum;
        float* at = g_attn_t + (size_t)b*25*784 + n;
        #pragma unroll
        for (int s = 0; s < 25; s++) at[(size_t)s*784] = e[s] * inv;
    }
    if (t == 0) g_cnt[b*7 + blockIdx.x] = 0;
}

// ---------------------------------------------------------------------------
// k_out: out[c,n] = x[c,n] + gamma * sum_s v[c,s]*attn_t[s,n]
// grid(7 n-tiles of 112, 8 c-tiles of 128, 16 b), 224 thr. thread 8c x 8n.
// ---------------------------------------------------------------------------
__global__ __launch_bounds__(224, 2) void k_out(const float* __restrict__ x,
                                                const float* __restrict__ gamma_p,
                                                float* __restrict__ out) {
    __shared__ float attn_ts[25*112];   // [s][n] straight coalesced copy
    __shared__ float v_ts[25*132];      // [s][c] transpose load
    int n0 = blockIdx.x * 112;
    int c0 = blockIdx.y * 128;
    int b  = blockIdx.z;
    int t = threadIdx.x;

    const float4* at4 = (const float4*)(g_attn_t + (size_t)b*25*784) + (n0 >> 2);
    #pragma unroll
    for (int u = 0; u < 4; u++) {
        int i = t + u*224;
        if (i < 700) {
            int s = i / 28, q = i - s*28;
            ((float4*)attn_ts)[s*28 + q] = at4[(size_t)s*196 + q];
        }
    }
    const float4* v4p = (const float4*)(g_v + (size_t)((b << 10) + c0)*32);
    #pragma unroll
    for (int u = 0; u < 5; u++) {
        int i = t + u*224;
        if (i < 1024) {
            int row = i >> 3, q = i & 7;
            float4 a4 = v4p[row*8 + q];
            int s = q*4;
            if (s   < 25) v_ts[(s  )*132 + row] = a4.x;
            if (s+1 < 25) v_ts[(s+1)*132 + row] = a4.y;
            if (s+2 < 25) v_ts[(s+2)*132 + row] = a4.z;
            if (s+3 < 25) v_ts[(s+3)*132 + row] = a4.w;
        }
    }
    __syncthreads();

    int ng = t % 14, cq = t / 14;       // 14 n-octets x 16 c-octets
    unsigned long long acc2[8][4] = {};
    #pragma unroll
    for (int s = 0; s < 25; s++) {
        float4 vlo = *(const float4*)&v_ts[s*132 + cq*8];
        float4 vhi = *(const float4*)&v_ts[s*132 + cq*8 + 4];
        const ulonglong2* ap = (const ulonglong2*)&attn_ts[s*112 + ng*8];
        ulonglong2 A0 = ap[0], A1 = ap[1];
        unsigned long long pv[8] = {
            pack2(vlo.x,vlo.x), pack2(vlo.y,vlo.y),
            pack2(vlo.z,vlo.z), pack2(vlo.w,vlo.w),
            pack2(vhi.x,vhi.x), pack2(vhi.y,vhi.y),
            pack2(vhi.z,vhi.z), pack2(vhi.w,vhi.w)};
        #pragma unroll
        for (int i = 0; i < 8; i++) {
            fma2(acc2[i][0], pv[i], A0.x);
            fma2(acc2[i][1], pv[i], A0.y);
            fma2(acc2[i][2], pv[i], A1.x);
            fma2(acc2[i][3], pv[i], A1.y);
        }
    }
    float gamma = gamma_p[0];
    #pragma unroll
    for (int i = 0; i < 8; i++) {
        int c = c0 + cq*8 + i;
        size_t off = (size_t)((b << 10) + c)*784 + n0 + ng*8;
        const float* xr = x + off;
        float* orow = out + off;
        float2 q0 = unpack2(acc2[i][0]), q1 = unpack2(acc2[i][1]);
        float2 q2 = unpack2(acc2[i][2]), q3 = unpack2(acc2[i][3]);
        float4 xa = *(const float4*)xr;
        float4 xc = *(const float4*)(xr + 4);
        *(float4*)orow = make_float4(fmaf(gamma,q0.x,xa.x), fmaf(gamma,q0.y,xa.y),
                                     fmaf(gamma,q1.x,xa.z), fmaf(gamma,q1.y,xa.w));
        *(float4*)(orow+4) = make_float4(fmaf(gamma,q2.x,xc.x), fmaf(gamma,q2.y,xc.y),
                                         fmaf(gamma,q3.x,xc.z), fmaf(gamma,q3.y,xc.w));
    }
}

// ---------------------------------------------------------------------------
extern "C" void kernel_launch(void* const* d_in, const int* in_sizes, int n_in,
                              void* d_out, int out_size) {
    const float* x_rgb  = (const float*)d_in[0];
    const float* x_skel = (const float*)d_in[1];
    const float* Wq     = (const float*)d_in[2];
    const float* bq     = (const float*)d_in[3];
    const float* Wk     = (const float*)d_in[4];
    const float* bk     = (const float*)d_in[5];
    const float* Wv     = (const float*)d_in[6];
    const float* bv     = (const float*)d_in[7];
    const float* gamma  = (const float*)d_in[8];
    float* out = (float*)d_out;

    k_prep  <<<1897, 128>>>(Wq, bq, Wk, bk, x_skel);
    k_gemm1 <<<dim3(17, 16), 256>>>(Wv, bv);
    k_energy<<<dim3(7, 16, 4), 224>>>(x_rgb);
    k_out   <<<dim3(7, 8, 16), 224>>>(x_rgb, gamma, out);
}

// round 16
// speedup vs baseline: 1.1328x; 1.0358x over previous
#include <cuda_runtime.h>
#include <cstdint>

// ---------------- scratch (device globals; zero-initialized) ---------------
__device__ float g_pooledp[16*256*32];     // [b][cs][32] padded, pads stay 0
__device__ float g_dots[1281];             // Wq^T bk | Wk^T bq | bq.bk
__device__ float g_wqk[1024*256];          // Wq^T Wk  [cr][cs]
__device__ float g_kq[16*1024*32];         // [b][cr][32]
__device__ float g_v[16*1024*32];          // [b][cr][32]
__device__ float g_bqk[16*32];             // [b][32]
__device__ float g_epart[2*16*784*32];     // [z][b][n][32]
__device__ float g_attn_t[16*25*784];      // [b][s][n]  TRANSPOSED attention
__device__ int   g_cnt[16*7];              // completion counters [b][ntile]

// ---------------- packed f32x2 helpers -------------------------------------
__device__ __forceinline__ unsigned long long pack2(float lo, float hi) {
    unsigned long long r;
    asm("mov.b64 %0, {%1,%2};" : "=l"(r) : "f"(lo), "f"(hi));
    return r;
}
__device__ __forceinline__ float2 unpack2(unsigned long long v) {
    float2 r;
    asm("mov.b64 {%0,%1}, %2;" : "=f"(r.x), "=f"(r.y) : "l"(v));
    return r;
}
__device__ __forceinline__ void fma2(unsigned long long& d,
                                     unsigned long long a,
                                     unsigned long long b) {
    asm("fma.rn.f32x2 %0, %1, %2, %0;" : "+l"(d) : "l"(a), "l"(b));
}

// ---------------------------------------------------------------------------
// k_prep: gemm0 (0..255) | dots1 (256..287) | dots2 (288..295) | dots3 (296)
//         | pool (297..1896)
// ---------------------------------------------------------------------------
__global__ __launch_bounds__(128) void k_prep(const float* __restrict__ Wq,
                                              const float* __restrict__ bq,
                                              const float* __restrict__ Wk,
                                              const float* __restrict__ bk,
                                              const float* __restrict__ xs_in) {
    __shared__ float sm[1664];
    int bid = blockIdx.x;
    int t = threadIdx.x;

    if (bid < 256) {
        float* As = sm;          // [16][32]
        float* Bs = sm + 512;    // [16][32]
        int m0 = (bid >> 3) * 32, n0 = (bid & 7) * 32;
        int tx = t & 7, ty = t >> 3;
        unsigned long long acc2[2][2] = {};
        for (int k0 = 0; k0 < 512; k0 += 16) {
            #pragma unroll
            for (int u = 0; u < 4; u++) {
                int idx = t + u * 128;
                int kk = idx >> 5, mm = idx & 31;
                As[idx] = Wq[(k0+kk)*1024 + m0 + mm];
                Bs[idx] = Wk[(k0+kk)*256 + n0 + mm];
            }
            __syncthreads();
            #pragma unroll
            for (int kk = 0; kk < 16; kk++) {
                float2 a2 = *(const float2*)&As[kk*32 + ty*2];
                ulonglong2 b2 = *(const ulonglong2*)&Bs[kk*32 + tx*4];
                unsigned long long pa0 = pack2(a2.x, a2.x);
                unsigned long long pa1 = pack2(a2.y, a2.y);
                fma2(acc2[0][0], pa0, b2.x);
                fma2(acc2[0][1], pa0, b2.y);
                fma2(acc2[1][0], pa1, b2.x);
                fma2(acc2[1][1], pa1, b2.y);
            }
            __syncthreads();
        }
        #pragma unroll
        for (int i = 0; i < 2; i++) {
            float2 p0 = unpack2(acc2[i][0]), p1 = unpack2(acc2[i][1]);
            *(float4*)&g_wqk[(m0 + ty*2 + i)*256 + n0 + tx*4] =
                make_float4(p0.x, p0.y, p1.x, p1.y);
        }
    } else if (bid < 288) {
        int lane = t & 31, slice = t >> 5;
        int c = (bid - 256) * 32 + lane;
        float acc = 0.f;
        int kbase = slice * 128;
        #pragma unroll 8
        for (int i = 0; i < 128; i++)
            acc += Wq[(kbase + i)*1024 + c] * bk[kbase + i];
        sm[t] = acc; __syncthreads();
        if (t < 32)
            g_dots[(bid - 256)*32 + t] = sm[t] + sm[t+32] + sm[t+64] + sm[t+96];
    } else if (bid < 296) {
        int lane = t & 31, slice = t >> 5;
        int c = (bid - 288) * 32 + lane;
        float acc = 0.f;
        int kbase = slice * 128;
        #pragma unroll 8
        for (int i = 0; i < 128; i++)
            acc += Wk[(kbase + i)*256 + c] * bq[kbase + i];
        sm[t] = acc; __syncthreads();
        if (t < 32)
            g_dots[1024 + (bid - 288)*32 + t] = sm[t] + sm[t+32] + sm[t+64] + sm[t+96];
    } else if (bid == 296) {
        float acc = 0.f;
        for (int i = t; i < 512; i += 128) acc += bq[i] * bk[i];
        sm[t] = acc; __syncthreads();
        for (int st = 64; st > 0; st >>= 1) {
            if (t < st) sm[t] += sm[t + st];
            __syncthreads();
        }
        if (t == 0) g_dots[1280] = sm[0];
    } else {
        int r0 = (bid - 297) * 64;
        const float* src = xs_in + (size_t)r0 * 25;
        for (int i = t; i < 1600; i += 128) sm[i] = src[i];
        __syncthreads();
        if (t < 64) {
            float s = 0.f;
            #pragma unroll
            for (int w = 0; w < 25; w++) s += sm[t*25 + w];
            int o = r0 + t;
            int bc = o / 25, s_idx = o - bc * 25;
            g_pooledp[bc*32 + s_idx] = s * (1.0f / 25.0f);
        }
    }
}

// ---------------------------------------------------------------------------
// k_gemm1: [kq; v; bqk](b) = [Wqk; Wv; wkbq] @ pooledp_b + bias
// grid(17, 16), 256 thr (8 warps). BM=128, S=32, BK=32. thread 4m x 4s.
// ---------------------------------------------------------------------------
__global__ __launch_bounds__(256) void k_gemm1(const float* __restrict__ Wv,
                                               const float* __restrict__ bv) {
    __shared__ float As[32*132];
    __shared__ float Bs[32*32];
    int bx = blockIdx.x;
    int b  = blockIdx.y;
    int m0 = bx * 128;
    int t = threadIdx.x;
    int row = t >> 1, half = t & 1;
    int tx = t & 7, ty = t >> 3;
    unsigned long long acc2[4][2] = {};

    const float* arow;
    bool arow_valid;
    if (bx < 8)       { arow = g_wqk + (size_t)(m0 + row) * 256; arow_valid = true; }
    else if (bx < 16) { arow = Wv + (size_t)(m0 - 1024 + row) * 256; arow_valid = true; }
    else              { arow = g_dots + 1024; arow_valid = (row == 0); }

    for (int k0 = 0; k0 < 256; k0 += 32) {
        if (arow_valid) {
            #pragma unroll
            for (int u = 0; u < 4; u++) {
                int koff = half*16 + u*4;
                float4 a4 = *(const float4*)&arow[k0 + koff];
                As[(koff+0)*132 + row] = a4.x;
                As[(koff+1)*132 + row] = a4.y;
                As[(koff+2)*132 + row] = a4.z;
                As[(koff+3)*132 + row] = a4.w;
            }
        } else {
            #pragma unroll
            for (int u = 0; u < 4; u++) {
                int koff = half*16 + u*4;
                As[(koff+0)*132 + row] = 0.f;
                As[(koff+1)*132 + row] = 0.f;
                As[(koff+2)*132 + row] = 0.f;
                As[(koff+3)*132 + row] = 0.f;
            }
        }
        const float4* bsrc = (const float4*)(g_pooledp + ((b << 8) + k0) * 32);
        ((float4*)Bs)[t] = bsrc[t];
        __syncthreads();
        #pragma unroll 8
        for (int kk = 0; kk < 32; kk++) {
            float4 a4 = *(const float4*)&As[kk*132 + ty*4];
            ulonglong2 b2 = *(const ulonglong2*)&Bs[kk*32 + tx*4];
            unsigned long long pa[4] = {pack2(a4.x,a4.x), pack2(a4.y,a4.y),
                                        pack2(a4.z,a4.z), pack2(a4.w,a4.w)};
            #pragma unroll
            for (int i = 0; i < 4; i++) {
                fma2(acc2[i][0], pa[i], b2.x);
                fma2(acc2[i][1], pa[i], b2.y);
            }
        }
        __syncthreads();
    }
    int s0 = tx * 4;
    #pragma unroll
    for (int i = 0; i < 4; i++) {
        int m = m0 + ty*4 + i;
        float2 p0 = unpack2(acc2[i][0]), p1 = unpack2(acc2[i][1]);
        if (bx < 8) {
            float d = g_dots[m];
            *(float4*)&g_kq[((b << 10) + m)*32 + s0] =
                make_float4(p0.x+d, p0.y+d, p1.x+d, p1.y+d);
        } else if (bx < 16) {
            float d = bv[m - 1024];
            *(float4*)&g_v[((b << 10) + (m - 1024))*32 + s0] =
                make_float4(p0.x+d, p0.y+d, p1.x+d, p1.y+d);
        } else if (m == 2048) {
            float d = g_dots[1280];
            *(float4*)&g_bqk[b*32 + s0] =
                make_float4(p0.x+d, p0.y+d, p1.x+d, p1.y+d);
        }
    }
}

// ---------------------------------------------------------------------------
// k_energy (mma.sync tf32): per (n-tile of 112, b, z-half of K):
//   E[112 pix][32 s] += x^T @ kq via m16n8k8 tf32 HMMA. Warps 0-6 own one
//   m16 tile each. smem strides padded for conflict-free fragment loads.
//   Last z-block sums 2 partials, softmaxes, writes transposed attn_t.
// grid(7, 16, 2), 256 thr.
// ---------------------------------------------------------------------------
__global__ __launch_bounds__(256) void k_energy(const float* __restrict__ x) {
    __shared__ float xs[64*120];    // [c][n] pad 120 -> banks 0/24/16/8
    __shared__ float kqs[64*40];    // [c][s] pad 40  -> banks 0/8/16/24
    __shared__ int s_last;
    int n0 = blockIdx.x * 112;
    int b  = blockIdx.y;
    int z  = blockIdx.z;
    int t = threadIdx.x;
    int wid = t >> 5, lane = t & 31;
    int r = lane >> 2, q = lane & 3;
    int c4 = t >> 2, q4 = t & 3;    // x-load mapping

    float d[4][4] = {};             // [s-tile][frag reg]

    for (int kc = 0; kc < 8; kc++) {
        int cbase = z*512 + kc*64;
        // xs: 64 c-rows x 112 px (each thread: 7 float4 in one row quarter)
        {
            const float4* xsrc = (const float4*)x
                + (size_t)((b << 10) + cbase + c4) * 196 + (n0 >> 2) + q4*7;
            float4* xdst = (float4*)&xs[c4*120 + q4*28];
            #pragma unroll
            for (int j = 0; j < 7; j++) xdst[j] = xsrc[j];
        }
        // kqs: 64 c-rows x 32 s
        {
            const float4* kq4p = (const float4*)g_kq;
            #pragma unroll
            for (int u = 0; u < 2; u++) {
                int idx = t + u*256;
                int c = idx >> 3, qq = idx & 7;
                *(float4*)&kqs[c*40 + qq*4] =
                    kq4p[(size_t)((b << 10) + cbase + c)*8 + qq];
            }
        }
        __syncthreads();
        if (wid < 7) {
            int nbase = wid * 16;
            #pragma unroll
            for (int k8 = 0; k8 < 8; k8++) {
                int c0 = k8 * 8;
                float a0 = xs[(c0+q)*120 + nbase + r];
                float a1 = xs[(c0+q)*120 + nbase + r + 8];
                float a2 = xs[(c0+q+4)*120 + nbase + r];
                float a3 = xs[(c0+q+4)*120 + nbase + r + 8];
                #pragma unroll
                for (int st = 0; st < 4; st++) {
                    float b0 = kqs[(c0+q)*40 + st*8 + r];
                    float b1 = kqs[(c0+q+4)*40 + st*8 + r];
                    asm volatile(
                        "mma.sync.aligned.m16n8k8.row.col.f32.tf32.tf32.f32 "
                        "{%0,%1,%2,%3}, {%4,%5,%6,%7}, {%8,%9}, {%0,%1,%2,%3};"
                        : "+f"(d[st][0]), "+f"(d[st][1]),
                          "+f"(d[st][2]), "+f"(d[st][3])
                        : "r"(__float_as_uint(a0)), "r"(__float_as_uint(a1)),
                          "r"(__float_as_uint(a2)), "r"(__float_as_uint(a3)),
                          "r"(__float_as_uint(b0)), "r"(__float_as_uint(b1)));
                }
            }
        }
        __syncthreads();
    }

    // write partials: d[st] covers rows (nloc, nloc+8), cols (st*8+2q, +1)
    if (wid < 7) {
        float* ep = g_epart + (size_t)(z*16 + b)*784*32;
        int n_lo = n0 + wid*16 + r;
        #pragma unroll
        for (int st = 0; st < 4; st++) {
            int sc = st*8 + 2*q;
            *(float2*)&ep[(size_t)n_lo*32 + sc] = make_float2(d[st][0], d[st][1]);
            *(float2*)&ep[(size_t)(n_lo+8)*32 + sc] = make_float2(d[st][2], d[st][3]);
        }
    }

    // ---- last-block-arrives softmax ----
    __threadfence();
    __syncthreads();
    if (t == 0)
        s_last = (atomicAdd(&g_cnt[b*7 + blockIdx.x], 1) == 1) ? 1 : 0;
    __syncthreads();
    if (s_last == 0) return;

    if (t < 112) {
        int n = n0 + t;
        const size_t part = (size_t)16*784*32;
        const float* base = g_epart + ((size_t)b*784 + n)*32;
        const float* bz = base + part;
        float e[25];
        #pragma unroll
        for (int j = 0; j < 6; j++) {
            float4 a = *(const float4*)(base + j*4);
            float4 c = *(const float4*)(bz + j*4);
            e[4*j+0] = a.x + c.x;
            e[4*j+1] = a.y + c.y;
            e[4*j+2] = a.z + c.z;
            if (4*j+3 < 25) e[4*j+3] = a.w + c.w;
        }
        e[24] = base[24] + bz[24];
        float mx = -1e30f;
        #pragma unroll
        for (int s = 0; s < 25; s++) {
            e[s] += g_bqk[b*32 + s];
            mx = fmaxf(mx, e[s]);
        }
        float sum = 0.f;
        #pragma unroll
        for (int s = 0; s < 25; s++) { e[s] = __expf(e[s] - mx); sum += e[s]; }
        float inv = 1.f / sum;
        float* at = g_attn_t + (size_t)b*25*784 + n;
        #pragma unroll
        for (int s = 0; s < 25; s++) at[(size_t)s*784] = e[s] * inv;
    }
    if (t == 0) g_cnt[b*7 + blockIdx.x] = 0;
}

// ---------------------------------------------------------------------------
// k_out: out[c,n] = x[c,n] + gamma * sum_s v[c,s]*attn_t[s,n]
// grid(7 n-tiles of 112, 8 c-tiles of 128, 16 b), 224 thr. thread 8c x 8n.
// ---------------------------------------------------------------------------
__global__ __launch_bounds__(224, 2) void k_out(const float* __restrict__ x,
                                                const float* __restrict__ gamma_p,
                                                float* __restrict__ out) {
    __shared__ float attn_ts[25*112];   // [s][n] straight coalesced copy
    __shared__ float v_ts[25*132];      // [s][c] transpose load
    int n0 = blockIdx.x * 112;
    int c0 = blockIdx.y * 128;
    int b  = blockIdx.z;
    int t = threadIdx.x;

    const float4* at4 = (const float4*)(g_attn_t + (size_t)b*25*784) + (n0 >> 2);
    #pragma unroll
    for (int u = 0; u < 4; u++) {
        int i = t + u*224;
        if (i < 700) {
            int s = i / 28, q = i - s*28;
            ((float4*)attn_ts)[s*28 + q] = at4[(size_t)s*196 + q];
        }
    }
    const float4* v4p = (const float4*)(g_v + (size_t)((b << 10) + c0)*32);
    #pragma unroll
    for (int u = 0; u < 5; u++) {
        int i = t + u*224;
        if (i < 1024) {
            int row = i >> 3, q = i & 7;
            float4 a4 = v4p[row*8 + q];
            int s = q*4;
            if (s   < 25) v_ts[(s  )*132 + row] = a4.x;
            if (s+1 < 25) v_ts[(s+1)*132 + row] = a4.y;
            if (s+2 < 25) v_ts[(s+2)*132 + row] = a4.z;
            if (s+3 < 25) v_ts[(s+3)*132 + row] = a4.w;
        }
    }
    __syncthreads();

    int ng = t % 14, cq = t / 14;       // 14 n-octets x 16 c-octets
    unsigned long long acc2[8][4] = {};
    #pragma unroll
    for (int s = 0; s < 25; s++) {
        float4 vlo = *(const float4*)&v_ts[s*132 + cq*8];
        float4 vhi = *(const float4*)&v_ts[s*132 + cq*8 + 4];
        const ulonglong2* ap = (const ulonglong2*)&attn_ts[s*112 + ng*8];
        ulonglong2 A0 = ap[0], A1 = ap[1];
        unsigned long long pv[8] = {
            pack2(vlo.x,vlo.x), pack2(vlo.y,vlo.y),
            pack2(vlo.z,vlo.z), pack2(vlo.w,vlo.w),
            pack2(vhi.x,vhi.x), pack2(vhi.y,vhi.y),
            pack2(vhi.z,vhi.z), pack2(vhi.w,vhi.w)};
        #pragma unroll
        for (int i = 0; i < 8; i++) {
            fma2(acc2[i][0], pv[i], A0.x);
            fma2(acc2[i][1], pv[i], A0.y);
            fma2(acc2[i][2], pv[i], A1.x);
            fma2(acc2[i][3], pv[i], A1.y);
        }
    }
    float gamma = gamma_p[0];
    #pragma unroll
    for (int i = 0; i < 8; i++) {
        int c = c0 + cq*8 + i;
        size_t off = (size_t)((b << 10) + c)*784 + n0 + ng*8;
        const float* xr = x + off;
        float* orow = out + off;
        float2 q0 = unpack2(acc2[i][0]), q1 = unpack2(acc2[i][1]);
        float2 q2 = unpack2(acc2[i][2]), q3 = unpack2(acc2[i][3]);
        float4 xa = *(const float4*)xr;
        float4 xc = *(const float4*)(xr + 4);
        *(float4*)orow = make_float4(fmaf(gamma,q0.x,xa.x), fmaf(gamma,q0.y,xa.y),
                                     fmaf(gamma,q1.x,xa.z), fmaf(gamma,q1.y,xa.w));
        *(float4*)(orow+4) = make_float4(fmaf(gamma,q2.x,xc.x), fmaf(gamma,q2.y,xc.y),
                                         fmaf(gamma,q3.x,xc.z), fmaf(gamma,q3.y,xc.w));
    }
}

// ---------------------------------------------------------------------------
extern "C" void kernel_launch(void* const* d_in, const int* in_sizes, int n_in,
                              void* d_out, int out_size) {
    const float* x_rgb  = (const float*)d_in[0];
    const float* x_skel = (const float*)d_in[1];
    const float* Wq     = (const float*)d_in[2];
    const float* bq     = (const float*)d_in[3];
    const float* Wk     = (const float*)d_in[4];
    const float* bk     = (const float*)d_in[5];
    const float* Wv     = (const float*)d_in[6];
    const float* bv     = (const float*)d_in[7];
    const float* gamma  = (const float*)d_in[8];
    float* out = (float*)d_out;

    k_prep  <<<1897, 128>>>(Wq, bq, Wk, bk, x_skel);
    k_gemm1 <<<dim3(17, 16), 256>>>(Wv, bv);
    k_energy<<<dim3(7, 16, 2), 256>>>(x_rgb);
    k_out   <<<dim3(7, 8, 16), 224>>>(x_rgb, gamma, out);
}

// round 17
// speedup vs baseline: 1.2137x; 1.0714x over previous
#include <cuda_runtime.h>
#include <cstdint>

// ---------------- scratch (device globals; zero-initialized) ---------------
__device__ float g_pooledp[16*256*32];     // [b][cs][32] padded, pads stay 0
__device__ float g_dots[1281];             // Wq^T bk | Wk^T bq | bq.bk
__device__ float g_wqk[1024*256];          // Wq^T Wk  [cr][cs]
__device__ float g_kq[16*1024*32];         // [b][cr][32]
__device__ float g_v[16*1024*32];          // [b][cr][32]
__device__ float g_bqk[16*32];             // [b][32]
__device__ float g_epart[2*16*784*32];     // [z][b][n][32]
__device__ float g_attn_t[16*25*784];      // [b][s][n]  TRANSPOSED attention
__device__ int   g_cnt[16*7];              // completion counters [b][ntile]

// ---------------- packed f32x2 helpers -------------------------------------
__device__ __forceinline__ unsigned long long pack2(float lo, float hi) {
    unsigned long long r;
    asm("mov.b64 %0, {%1,%2};" : "=l"(r) : "f"(lo), "f"(hi));
    return r;
}
__device__ __forceinline__ float2 unpack2(unsigned long long v) {
    float2 r;
    asm("mov.b64 {%0,%1}, %2;" : "=f"(r.x), "=f"(r.y) : "l"(v));
    return r;
}
__device__ __forceinline__ void fma2(unsigned long long& d,
                                     unsigned long long a,
                                     unsigned long long b) {
    asm("fma.rn.f32x2 %0, %1, %2, %0;" : "+l"(d) : "l"(a), "l"(b));
}

// ---------------------------------------------------------------------------
// k_prep: gemm0 (0..255) | dots1 (256..287) | dots2 (288..295) | dots3 (296)
//         | pool (297..1896)
// ---------------------------------------------------------------------------
__global__ __launch_bounds__(128) void k_prep(const float* __restrict__ Wq,
                                              const float* __restrict__ bq,
                                              const float* __restrict__ Wk,
                                              const float* __restrict__ bk,
                                              const float* __restrict__ xs_in) {
    __shared__ float sm[1664];
    int bid = blockIdx.x;
    int t = threadIdx.x;

    if (bid < 256) {
        float* As = sm;          // [16][32]
        float* Bs = sm + 512;    // [16][32]
        int m0 = (bid >> 3) * 32, n0 = (bid & 7) * 32;
        int tx = t & 7, ty = t >> 3;
        unsigned long long acc2[2][2] = {};
        for (int k0 = 0; k0 < 512; k0 += 16) {
            #pragma unroll
            for (int u = 0; u < 4; u++) {
                int idx = t + u * 128;
                int kk = idx >> 5, mm = idx & 31;
                As[idx] = Wq[(k0+kk)*1024 + m0 + mm];
                Bs[idx] = Wk[(k0+kk)*256 + n0 + mm];
            }
            __syncthreads();
            #pragma unroll
            for (int kk = 0; kk < 16; kk++) {
                float2 a2 = *(const float2*)&As[kk*32 + ty*2];
                ulonglong2 b2 = *(const ulonglong2*)&Bs[kk*32 + tx*4];
                unsigned long long pa0 = pack2(a2.x, a2.x);
                unsigned long long pa1 = pack2(a2.y, a2.y);
                fma2(acc2[0][0], pa0, b2.x);
                fma2(acc2[0][1], pa0, b2.y);
                fma2(acc2[1][0], pa1, b2.x);
                fma2(acc2[1][1], pa1, b2.y);
            }
            __syncthreads();
        }
        #pragma unroll
        for (int i = 0; i < 2; i++) {
            float2 p0 = unpack2(acc2[i][0]), p1 = unpack2(acc2[i][1]);
            *(float4*)&g_wqk[(m0 + ty*2 + i)*256 + n0 + tx*4] =
                make_float4(p0.x, p0.y, p1.x, p1.y);
        }
    } else if (bid < 288) {
        int lane = t & 31, slice = t >> 5;
        int c = (bid - 256) * 32 + lane;
        float acc = 0.f;
        int kbase = slice * 128;
        #pragma unroll 8
        for (int i = 0; i < 128; i++)
            acc += Wq[(kbase + i)*1024 + c] * bk[kbase + i];
        sm[t] = acc; __syncthreads();
        if (t < 32)
            g_dots[(bid - 256)*32 + t] = sm[t] + sm[t+32] + sm[t+64] + sm[t+96];
    } else if (bid < 296) {
        int lane = t & 31, slice = t >> 5;
        int c = (bid - 288) * 32 + lane;
        float acc = 0.f;
        int kbase = slice * 128;
        #pragma unroll 8
        for (int i = 0; i < 128; i++)
            acc += Wk[(kbase + i)*256 + c] * bq[kbase + i];
        sm[t] = acc; __syncthreads();
        if (t < 32)
            g_dots[1024 + (bid - 288)*32 + t] = sm[t] + sm[t+32] + sm[t+64] + sm[t+96];
    } else if (bid == 296) {
        float acc = 0.f;
        for (int i = t; i < 512; i += 128) acc += bq[i] * bk[i];
        sm[t] = acc; __syncthreads();
        for (int st = 64; st > 0; st >>= 1) {
            if (t < st) sm[t] += sm[t + st];
            __syncthreads();
        }
        if (t == 0) g_dots[1280] = sm[0];
    } else {
        int r0 = (bid - 297) * 64;
        const float* src = xs_in + (size_t)r0 * 25;
        for (int i = t; i < 1600; i += 128) sm[i] = src[i];
        __syncthreads();
        if (t < 64) {
            float s = 0.f;
            #pragma unroll
            for (int w = 0; w < 25; w++) s += sm[t*25 + w];
            int o = r0 + t;
            int bc = o / 25, s_idx = o - bc * 25;
            g_pooledp[bc*32 + s_idx] = s * (1.0f / 25.0f);
        }
    }
}

// ---------------------------------------------------------------------------
// k_gemm1: [kq; v; bqk](b) = [Wqk; Wv; wkbq] @ pooledp_b + bias
// grid(17, 16), 256 thr (8 warps). BM=128, S=32, BK=32. thread 4m x 4s.
// ---------------------------------------------------------------------------
__global__ __launch_bounds__(256) void k_gemm1(const float* __restrict__ Wv,
                                               const float* __restrict__ bv) {
    __shared__ float As[32*132];
    __shared__ float Bs[32*32];
    int bx = blockIdx.x;
    int b  = blockIdx.y;
    int m0 = bx * 128;
    int t = threadIdx.x;
    int row = t >> 1, half = t & 1;
    int tx = t & 7, ty = t >> 3;
    unsigned long long acc2[4][2] = {};

    const float* arow;
    bool arow_valid;
    if (bx < 8)       { arow = g_wqk + (size_t)(m0 + row) * 256; arow_valid = true; }
    else if (bx < 16) { arow = Wv + (size_t)(m0 - 1024 + row) * 256; arow_valid = true; }
    else              { arow = g_dots + 1024; arow_valid = (row == 0); }

    for (int k0 = 0; k0 < 256; k0 += 32) {
        if (arow_valid) {
            #pragma unroll
            for (int u = 0; u < 4; u++) {
                int koff = half*16 + u*4;
                float4 a4 = *(const float4*)&arow[k0 + koff];
                As[(koff+0)*132 + row] = a4.x;
                As[(koff+1)*132 + row] = a4.y;
                As[(koff+2)*132 + row] = a4.z;
                As[(koff+3)*132 + row] = a4.w;
            }
        } else {
            #pragma unroll
            for (int u = 0; u < 4; u++) {
                int koff = half*16 + u*4;
                As[(koff+0)*132 + row] = 0.f;
                As[(koff+1)*132 + row] = 0.f;
                As[(koff+2)*132 + row] = 0.f;
                As[(koff+3)*132 + row] = 0.f;
            }
        }
        const float4* bsrc = (const float4*)(g_pooledp + ((b << 8) + k0) * 32);
        ((float4*)Bs)[t] = bsrc[t];
        __syncthreads();
        #pragma unroll 8
        for (int kk = 0; kk < 32; kk++) {
            float4 a4 = *(const float4*)&As[kk*132 + ty*4];
            ulonglong2 b2 = *(const ulonglong2*)&Bs[kk*32 + tx*4];
            unsigned long long pa[4] = {pack2(a4.x,a4.x), pack2(a4.y,a4.y),
                                        pack2(a4.z,a4.z), pack2(a4.w,a4.w)};
            #pragma unroll
            for (int i = 0; i < 4; i++) {
                fma2(acc2[i][0], pa[i], b2.x);
                fma2(acc2[i][1], pa[i], b2.y);
            }
        }
        __syncthreads();
    }
    int s0 = tx * 4;
    #pragma unroll
    for (int i = 0; i < 4; i++) {
        int m = m0 + ty*4 + i;
        float2 p0 = unpack2(acc2[i][0]), p1 = unpack2(acc2[i][1]);
        if (bx < 8) {
            float d = g_dots[m];
            *(float4*)&g_kq[((b << 10) + m)*32 + s0] =
                make_float4(p0.x+d, p0.y+d, p1.x+d, p1.y+d);
        } else if (bx < 16) {
            float d = bv[m - 1024];
            *(float4*)&g_v[((b << 10) + (m - 1024))*32 + s0] =
                make_float4(p0.x+d, p0.y+d, p1.x+d, p1.y+d);
        } else if (m == 2048) {
            float d = g_dots[1280];
            *(float4*)&g_bqk[b*32 + s0] =
                make_float4(p0.x+d, p0.y+d, p1.x+d, p1.y+d);
        }
    }
}

// ---------------------------------------------------------------------------
// k_energy (mma.sync tf32): grid(7, 16, 2), 256 thr.  (R16-measured design)
// ---------------------------------------------------------------------------
__global__ __launch_bounds__(256) void k_energy(const float* __restrict__ x) {
    __shared__ float xs[64*120];    // [c][n] pad 120
    __shared__ float kqs[64*40];    // [c][s] pad 40
    __shared__ int s_last;
    int n0 = blockIdx.x * 112;
    int b  = blockIdx.y;
    int z  = blockIdx.z;
    int t = threadIdx.x;
    int wid = t >> 5, lane = t & 31;
    int r = lane >> 2, q = lane & 3;
    int c4 = t >> 2, q4 = t & 3;

    float d[4][4] = {};

    for (int kc = 0; kc < 8; kc++) {
        int cbase = z*512 + kc*64;
        {
            const float4* xsrc = (const float4*)x
                + (size_t)((b << 10) + cbase + c4) * 196 + (n0 >> 2) + q4*7;
            float4* xdst = (float4*)&xs[c4*120 + q4*28];
            #pragma unroll
            for (int j = 0; j < 7; j++) xdst[j] = xsrc[j];
        }
        {
            const float4* kq4p = (const float4*)g_kq;
            #pragma unroll
            for (int u = 0; u < 2; u++) {
                int idx = t + u*256;
                int c = idx >> 3, qq = idx & 7;
                *(float4*)&kqs[c*40 + qq*4] =
                    kq4p[(size_t)((b << 10) + cbase + c)*8 + qq];
            }
        }
        __syncthreads();
        if (wid < 7) {
            int nbase = wid * 16;
            #pragma unroll
            for (int k8 = 0; k8 < 8; k8++) {
                int c0 = k8 * 8;
                float a0 = xs[(c0+q)*120 + nbase + r];
                float a1 = xs[(c0+q)*120 + nbase + r + 8];
                float a2 = xs[(c0+q+4)*120 + nbase + r];
                float a3 = xs[(c0+q+4)*120 + nbase + r + 8];
                #pragma unroll
                for (int st = 0; st < 4; st++) {
                    float b0 = kqs[(c0+q)*40 + st*8 + r];
                    float b1 = kqs[(c0+q+4)*40 + st*8 + r];
                    asm volatile(
                        "mma.sync.aligned.m16n8k8.row.col.f32.tf32.tf32.f32 "
                        "{%0,%1,%2,%3}, {%4,%5,%6,%7}, {%8,%9}, {%0,%1,%2,%3};"
                        : "+f"(d[st][0]), "+f"(d[st][1]),
                          "+f"(d[st][2]), "+f"(d[st][3])
                        : "r"(__float_as_uint(a0)), "r"(__float_as_uint(a1)),
                          "r"(__float_as_uint(a2)), "r"(__float_as_uint(a3)),
                          "r"(__float_as_uint(b0)), "r"(__float_as_uint(b1)));
                }
            }
        }
        __syncthreads();
    }

    if (wid < 7) {
        float* ep = g_epart + (size_t)(z*16 + b)*784*32;
        int n_lo = n0 + wid*16 + r;
        #pragma unroll
        for (int st = 0; st < 4; st++) {
            int sc = st*8 + 2*q;
            *(float2*)&ep[(size_t)n_lo*32 + sc] = make_float2(d[st][0], d[st][1]);
            *(float2*)&ep[(size_t)(n_lo+8)*32 + sc] = make_float2(d[st][2], d[st][3]);
        }
    }

    __threadfence();
    __syncthreads();
    if (t == 0)
        s_last = (atomicAdd(&g_cnt[b*7 + blockIdx.x], 1) == 1) ? 1 : 0;
    __syncthreads();
    if (s_last == 0) return;

    if (t < 112) {
        int n = n0 + t;
        const size_t part = (size_t)16*784*32;
        const float* base = g_epart + ((size_t)b*784 + n)*32;
        const float* bz = base + part;
        float e[25];
        #pragma unroll
        for (int j = 0; j < 6; j++) {
            float4 a = *(const float4*)(base + j*4);
            float4 c = *(const float4*)(bz + j*4);
            e[4*j+0] = a.x + c.x;
            e[4*j+1] = a.y + c.y;
            e[4*j+2] = a.z + c.z;
            if (4*j+3 < 25) e[4*j+3] = a.w + c.w;
        }
        e[24] = base[24] + bz[24];
        float mx = -1e30f;
        #pragma unroll
        for (int s = 0; s < 25; s++) {
            e[s] += g_bqk[b*32 + s];
            mx = fmaxf(mx, e[s]);
        }
        float sum = 0.f;
        #pragma unroll
        for (int s = 0; s < 25; s++) { e[s] = __expf(e[s] - mx); sum += e[s]; }
        float inv = 1.f / sum;
        float* at = g_attn_t + (size_t)b*25*784 + n;
        #pragma unroll
        for (int s = 0; s < 25; s++) at[(size_t)s*784] = e[s] * inv;
    }
    if (t == 0) g_cnt[b*7 + blockIdx.x] = 0;
}

// ---------------------------------------------------------------------------
// k_out (mma.sync tf32): out[c,n] = x[c,n] + gamma * sum_s v[c,s]*attn_t[s,n]
// grid(7 n-tiles of 112, 8 c-tiles of 128, 16 b), 256 thr (8 warps).
// Warp w owns c-stripe [c0+16w, +16) x all 112 n. K=s padded 25->32.
// ---------------------------------------------------------------------------
__global__ __launch_bounds__(256, 2) void k_out(const float* __restrict__ x,
                                                const float* __restrict__ gamma_p,
                                                float* __restrict__ out) {
    __shared__ float v_s[128*36];    // [c][s] pad 36 -> A-frag banks 4r+q
    __shared__ float at_s[32*120];   // [s][n] pad 120 -> B-frag banks 24q+r
    int n0 = blockIdx.x * 112;
    int c0 = blockIdx.y * 128;
    int b  = blockIdx.z;
    int t = threadIdx.x;
    int wid = t >> 5, lane = t & 31;
    int r = lane >> 2, q = lane & 3;

    // v: 128 rows x 8 float4, straight copy into padded rows
    const float4* v4p = (const float4*)(g_v + (size_t)((b << 10) + c0)*32);
    #pragma unroll
    for (int u = 0; u < 4; u++) {
        int i = t + u*256;
        int row = i >> 3, qq = i & 7;
        *(float4*)&v_s[row*36 + qq*4] = v4p[row*8 + qq];
    }
    // attn rows 0..24: straight copy; rows 25..31: zero (K-pad)
    const float4* at4 = (const float4*)(g_attn_t + (size_t)b*25*784 + n0);
    #pragma unroll
    for (int u = 0; u < 3; u++) {
        int i = t + u*256;
        if (i < 700) {
            int s = i / 28, qq = i - s*28;
            *(float4*)&at_s[s*120 + qq*4] = at4[(size_t)s*196 + qq];
        }
    }
    for (int i = t; i < 7*120; i += 256) at_s[25*120 + i] = 0.f;
    __syncthreads();

    float d[14][4] = {};
    int crow = wid * 16;
    #pragma unroll
    for (int ks = 0; ks < 4; ks++) {
        uint32_t a0 = __float_as_uint(v_s[(crow+r  )*36 + ks*8 + q]);
        uint32_t a1 = __float_as_uint(v_s[(crow+r+8)*36 + ks*8 + q]);
        uint32_t a2 = __float_as_uint(v_s[(crow+r  )*36 + ks*8 + q+4]);
        uint32_t a3 = __float_as_uint(v_s[(crow+r+8)*36 + ks*8 + q+4]);
        #pragma unroll
        for (int nt = 0; nt < 14; nt++) {
            uint32_t b0 = __float_as_uint(at_s[(ks*8+q  )*120 + nt*8 + r]);
            uint32_t b1 = __float_as_uint(at_s[(ks*8+q+4)*120 + nt*8 + r]);
            asm volatile(
                "mma.sync.aligned.m16n8k8.row.col.f32.tf32.tf32.f32 "
                "{%0,%1,%2,%3}, {%4,%5,%6,%7}, {%8,%9}, {%0,%1,%2,%3};"
                : "+f"(d[nt][0]), "+f"(d[nt][1]),
                  "+f"(d[nt][2]), "+f"(d[nt][3])
                : "r"(a0), "r"(a1), "r"(a2), "r"(a3), "r"(b0), "r"(b1));
        }
    }

    float gamma = gamma_p[0];
    size_t rowbase0 = (size_t)((b << 10) + c0 + crow + r)*784 + n0 + 2*q;
    size_t rowbase1 = rowbase0 + (size_t)8*784;
    #pragma unroll
    for (int nt = 0; nt < 14; nt++) {
        size_t off0 = rowbase0 + nt*8;
        size_t off1 = rowbase1 + nt*8;
        float2 x0 = *(const float2*)(x + off0);
        float2 x1 = *(const float2*)(x + off1);
        *(float2*)(out + off0) = make_float2(fmaf(gamma, d[nt][0], x0.x),
                                             fmaf(gamma, d[nt][1], x0.y));
        *(float2*)(out + off1) = make_float2(fmaf(gamma, d[nt][2], x1.x),
                                             fmaf(gamma, d[nt][3], x1.y));
    }
}

// ---------------------------------------------------------------------------
extern "C" void kernel_launch(void* const* d_in, const int* in_sizes, int n_in,
                              void* d_out, int out_size) {
    const float* x_rgb  = (const float*)d_in[0];
    const float* x_skel = (const float*)d_in[1];
    const float* Wq     = (const float*)d_in[2];
    const float* bq     = (const float*)d_in[3];
    const float* Wk     = (const float*)d_in[4];
    const float* bk     = (const float*)d_in[5];
    const float* Wv     = (const float*)d_in[6];
    const float* bv     = (const float*)d_in[7];
    const float* gamma  = (const float*)d_in[8];
    float* out = (float*)d_out;

    k_prep  <<<1897, 128>>>(Wq, bq, Wk, bk, x_skel);
    k_gemm1 <<<dim3(17, 16), 256>>>(Wv, bv);
    k_energy<<<dim3(7, 16, 2), 256>>>(x_rgb);
    k_out   <<<dim3(7, 8, 16), 256>>>(x_rgb, gamma, out);
}